// round 7
// baseline (speedup 1.0000x reference)
#include <cuda_runtime.h>
#include <cstdint>

// ---------------------------------------------------------------------------
// SRU forward on sm_100: tf32 mma.sync GEMM (pipelined fragments) + scan.
// L=1024, B=16, D=HIDDEN=2048.
// ---------------------------------------------------------------------------

#define L_DIM 1024
#define B_DIM 16
#define D_DIM 2048
#define H_DIM 2048
#define M_DIM (L_DIM * B_DIM)   // 16384
#define N_DIM (3 * H_DIM)       // 6144
#define K_DIM D_DIM             // 2048
#define PLANE ((size_t)M_DIM * H_DIM)

// GEMM tiling
#define BM 128
#define BN 256
#define BK 32
#define KITERS (K_DIM / BK)      // 64
#define STAGES 3

#define A_STAGE_BYTES (BM * 128)
#define B_STAGE_BYTES (BN * 128)
#define STAGE_BYTES (A_STAGE_BYTES + B_STAGE_BYTES)      // 48 KB
#define SMEM_TOTAL (STAGES * STAGE_BYTES)                // 144 KB

// ------------------------- device scratch (no mallocs) ----------------------
__device__ float g_A[(size_t)M_DIM * K_DIM];   // tf32-rounded x (MxK)
__device__ float g_B[(size_t)N_DIM * K_DIM];   // tf32-rounded W^T (NxK)
__device__ float g_U[3 * PLANE];               // U split into 3 planes [M,H]

// ------------------------------ PTX helpers ---------------------------------
__device__ __forceinline__ uint32_t smem_u32(const void* p) {
    uint32_t a;
    asm("{ .reg .u64 t; cvta.to.shared.u64 t, %1; cvt.u32.u64 %0, t; }"
        : "=r"(a) : "l"(p));
    return a;
}

__device__ __forceinline__ float tf32_rna(float x) {
    uint32_t u;
    asm("cvt.rna.tf32.f32 %0, %1;" : "=r"(u) : "f"(x));
    return __uint_as_float(u);
}

__device__ __forceinline__ void cp_async16(uint32_t smem_dst, const void* gmem_src) {
    size_t g = __cvta_generic_to_global(gmem_src);
    asm volatile("cp.async.cg.shared.global [%0], [%1], 16;"
                 :: "r"(smem_dst), "l"(g) : "memory");
}
__device__ __forceinline__ void cp_commit() {
    asm volatile("cp.async.commit_group;" ::: "memory");
}
__device__ __forceinline__ void cp_wait1() {
    asm volatile("cp.async.wait_group 1;" ::: "memory");
}

__device__ __forceinline__ uint32_t sw128(uint32_t off) {
    return off ^ ((off >> 3) & 0x70);
}

__device__ __forceinline__ void ldsm4(uint32_t* r, uint32_t addr) {
    asm volatile("ldmatrix.sync.aligned.m8n8.x4.shared.b16 {%0,%1,%2,%3}, [%4];"
                 : "=r"(r[0]), "=r"(r[1]), "=r"(r[2]), "=r"(r[3]) : "r"(addr));
}

__device__ __forceinline__ void mma_tf32(float* c, const uint32_t* a,
                                         uint32_t b0, uint32_t b1) {
    asm volatile(
        "mma.sync.aligned.m16n8k8.row.col.f32.tf32.tf32.f32 "
        "{%0,%1,%2,%3}, {%4,%5,%6,%7}, {%8,%9}, {%0,%1,%2,%3};"
        : "+f"(c[0]), "+f"(c[1]), "+f"(c[2]), "+f"(c[3])
        : "r"(a[0]), "r"(a[1]), "r"(a[2]), "r"(a[3]), "r"(b0), "r"(b1));
}

// --------------------------- prep kernels -----------------------------------
__global__ void conv_x_kernel(const float4* __restrict__ x) {
    int i = blockIdx.x * blockDim.x + threadIdx.x;
    float4 v = x[i];
    float4 o;
    o.x = tf32_rna(v.x); o.y = tf32_rna(v.y);
    o.z = tf32_rna(v.z); o.w = tf32_rna(v.w);
    reinterpret_cast<float4*>(g_A)[i] = o;
}

// W (K, N) fp32 -> g_B (N, K), tf32-rounded
__global__ void transpose_w_kernel(const float* __restrict__ w) {
    __shared__ float t[32][33];
    int n = blockIdx.x * 32 + threadIdx.x;
    int k0 = blockIdx.y * 32;
#pragma unroll
    for (int j = 0; j < 4; j++) {
        int k = k0 + threadIdx.y + j * 8;
        t[threadIdx.y + j * 8][threadIdx.x] = w[(size_t)k * N_DIM + n];
    }
    __syncthreads();
#pragma unroll
    for (int j = 0; j < 4; j++) {
        int nn = blockIdx.x * 32 + threadIdx.y + j * 8;
        g_B[(size_t)nn * K_DIM + k0 + threadIdx.x] =
            tf32_rna(t[threadIdx.x][threadIdx.y + j * 8]);
    }
}

// ----------------------------- GEMM kernel ----------------------------------
// 256 threads, 8 warps in 2(M) x 4(N), warp tile 64x64, mma m16n8k8 tf32.
__device__ __forceinline__ void load_tile(int s, int kt, int m0, int n0,
                                          uint32_t sb, int tid) {
    uint32_t abase = sb + s * STAGE_BYTES;
    uint32_t bbase = abase + A_STAGE_BYTES;
    int k0 = kt * BK;
#pragma unroll
    for (int i = 0; i < 4; i++) {
        int idx = tid + i * 256;
        uint32_t off = idx * 16;
        int r = off >> 7;
        int c = off & 127;
        const char* src = (const char*)g_A + (((size_t)(m0 + r) * K_DIM + k0) * 4 + c);
        cp_async16(abase + sw128(off), src);
    }
#pragma unroll
    for (int i = 0; i < 8; i++) {
        int idx = tid + i * 256;
        uint32_t off = idx * 16;
        int r = off >> 7;
        int c = off & 127;
        const char* src = (const char*)g_B + (((size_t)(n0 + r) * K_DIM + k0) * 4 + c);
        cp_async16(bbase + sw128(off), src);
    }
}

__global__ void __launch_bounds__(256, 1)
gemm_tf32_kernel() {
    extern __shared__ char smem[];
    uint32_t sb = smem_u32(smem);
    int tid = threadIdx.x;
    int wid = tid >> 5;
    int lane = tid & 31;
    int n0 = blockIdx.x * BN;
    int m0 = blockIdx.y * BM;
    int wm = wid & 1;        // 0..1 (M)
    int wn = wid >> 1;       // 0..3 (N)

    // ldmatrix per-lane PRE-SWIZZLED stage-relative offsets.
    // k-step advance: ks*32 toggles only bits [5:6]; the sw128 XOR mask is
    // computed from bits >=7, which k-advance never changes, so
    // sw128(off + ks*32) == sw128(off) ^ (ks*32).
    int sub = lane >> 3;
    int r8 = lane & 7;
    uint32_t a_row = wm * 64 + ((sub & 1) << 3) + r8;
    uint32_t a_kb = (sub >> 1) * 16;
    uint32_t b_row = wn * 64 + ((sub >> 1) << 3) + r8;
    uint32_t b_kb = (sub & 1) * 16;

    uint32_t a_sw[4], b_sw[4];
#pragma unroll
    for (int mt = 0; mt < 4; mt++)
        a_sw[mt] = sw128((a_row + mt * 16) * 128 + a_kb);
#pragma unroll
    for (int np = 0; np < 4; np++)
        b_sw[np] = sw128((b_row + np * 16) * 128 + b_kb);

    float acc[4][8][4];
#pragma unroll
    for (int mt = 0; mt < 4; mt++)
#pragma unroll
        for (int nt = 0; nt < 8; nt++)
#pragma unroll
            for (int q = 0; q < 4; q++) acc[mt][nt][q] = 0.0f;

    load_tile(0, 0, m0, n0, sb, tid);
    cp_commit();
    load_tile(1, 1, m0, n0, sb, tid);
    cp_commit();

    for (int kt = 0; kt < KITERS; kt++) {
        int s = kt % STAGES;
        cp_wait1();
        __syncthreads();

        if (kt + 2 < KITERS) {
            load_tile((kt + 2) % STAGES, kt + 2, m0, n0, sb, tid);
        }
        cp_commit();

        uint32_t abase = sb + s * STAGE_BYTES;
        uint32_t bbase = abase + A_STAGE_BYTES;

        // double-buffered fragments over ks
        uint32_t af[2][4][4], bf[2][4][4];
#pragma unroll
        for (int mt = 0; mt < 4; mt++) ldsm4(af[0][mt], abase + a_sw[mt]);
#pragma unroll
        for (int np = 0; np < 4; np++) ldsm4(bf[0][np], bbase + b_sw[np]);

#pragma unroll
        for (int ks = 0; ks < 4; ks++) {
            int cur = ks & 1;
            int nxt = cur ^ 1;
            if (ks < 3) {
                uint32_t kx = (uint32_t)(ks + 1) << 5;
#pragma unroll
                for (int mt = 0; mt < 4; mt++)
                    ldsm4(af[nxt][mt], abase + (a_sw[mt] ^ kx));
#pragma unroll
                for (int np = 0; np < 4; np++)
                    ldsm4(bf[nxt][np], bbase + (b_sw[np] ^ kx));
            }
#pragma unroll
            for (int mt = 0; mt < 4; mt++)
#pragma unroll
                for (int nt = 0; nt < 8; nt++) {
                    uint32_t b0 = bf[cur][nt >> 1][(nt & 1) * 2];
                    uint32_t b1 = bf[cur][nt >> 1][(nt & 1) * 2 + 1];
                    mma_tf32(acc[mt][nt], af[cur][mt], b0, b1);
                }
        }
    }

    // epilogue: scatter into 3 planes (u_j[row, h], n = 3h + j)
    int g = lane >> 2;
    int tig = lane & 3;
#pragma unroll
    for (int mt = 0; mt < 4; mt++) {
        int row0 = m0 + wm * 64 + mt * 16 + g;
#pragma unroll
        for (int nt = 0; nt < 8; nt++) {
            int colb = n0 + wn * 64 + nt * 8 + tig * 2;
#pragma unroll
            for (int e = 0; e < 2; e++) {
                int c = colb + e;
                int h = c / 3;
                int j = c - 3 * h;
                float* pl = g_U + (size_t)j * PLANE;
                pl[(size_t)row0 * H_DIM + h] = acc[mt][nt][e];
                pl[(size_t)(row0 + 8) * H_DIM + h] = acc[mt][nt][2 + e];
            }
        }
    }
}

// ----------------------------- scan kernel ----------------------------------
__device__ __forceinline__ float sigm(float z) {
    return __fdividef(1.0f, 1.0f + __expf(-z));
}

#define SBLK 8

__global__ void __launch_bounds__(128)
scan_kernel(const float* __restrict__ x, const float* __restrict__ wc,
            const float* __restrict__ bias, float* __restrict__ out,
            int out_size) {
    int gidx = blockIdx.x * blockDim.x + threadIdx.x;  // 0..32767
    int b = gidx >> 11;
    int h = gidx & 2047;
    float wcf = wc[h];
    float wcr = wc[H_DIM + h];
    float bf = bias[h];
    float br = bias[H_DIM + h];
    const float sx = 1.7320508075688772f;  // sqrt(1 + 2*exp(0))

    const size_t step = (size_t)B_DIM * H_DIM;       // per-l stride (planes & x & out)
    const float* U0 = g_U + (size_t)b * H_DIM + h;   // plane 0
    const float* U1 = U0 + PLANE;
    const float* U2 = U0 + 2 * PLANE;
    const float* xbase = x + (size_t)b * D_DIM + h;
    float* obase = out + (size_t)b * H_DIM + h;

    float A0[SBLK], A1[SBLK], A2[SBLK], A3[SBLK];
    float Bb0[SBLK], Bb1[SBLK], Bb2[SBLK], Bb3[SBLK];

#define LOADBLK(l0, d0, d1, d2, d3)                                        \
    {                                                                      \
        size_t o_ = (size_t)(l0) * step;                                   \
        _Pragma("unroll") for (int i = 0; i < SBLK; i++) {                 \
            d0[i] = U0[o_]; d1[i] = U1[o_]; d2[i] = U2[o_];                \
            d3[i] = xbase[o_];                                             \
            o_ += step;                                                    \
        }                                                                  \
    }

#define COMPBLK(l0, d0, d1, d2, d3)                                        \
    {                                                                      \
        float* op_ = obase + (size_t)(l0) * step;                          \
        _Pragma("unroll") for (int i = 0; i < SBLK; i++) {                 \
            float u0 = d0[i];                                              \
            float u1 = d1[i] + bf;                                         \
            float u2 = d2[i] + br;                                         \
            float xv = d3[i] * sx;                                         \
            float f = sigm(fmaf(c, wcf, u1));                              \
            c = fmaf(c - u0, f, u0);                                       \
            float r = sigm(fmaf(c, wcr, u2));                              \
            *op_ = fmaf(c - xv, r, xv);                                    \
            op_ += step;                                                   \
        }                                                                  \
    }

    float c = 0.0f;
    LOADBLK(0, A0, A1, A2, A3);
    for (int l0 = 0; l0 < L_DIM; l0 += 2 * SBLK) {
        LOADBLK(l0 + SBLK, Bb0, Bb1, Bb2, Bb3);
        COMPBLK(l0, A0, A1, A2, A3);
        if (l0 + 2 * SBLK < L_DIM) {
            LOADBLK(l0 + 2 * SBLK, A0, A1, A2, A3);
        }
        COMPBLK(l0 + SBLK, Bb0, Bb1, Bb2, Bb3);
    }

    if (out_size >= M_DIM * H_DIM + B_DIM * H_DIM) {
        out[(size_t)M_DIM * H_DIM + gidx] = c;  // c_last
    }
}

// ------------------------------ launcher ------------------------------------
extern "C" void kernel_launch(void* const* d_in, const int* in_sizes, int n_in,
                              void* d_out, int out_size) {
    (void)in_sizes; (void)n_in;
    const float* x    = (const float*)d_in[0];
    const float* w    = (const float*)d_in[1];
    const float* wc   = (const float*)d_in[2];
    const float* bias = (const float*)d_in[3];
    float* out = (float*)d_out;

    cudaFuncSetAttribute(gemm_tf32_kernel,
                         cudaFuncAttributeMaxDynamicSharedMemorySize, SMEM_TOTAL);

    conv_x_kernel<<<(M_DIM * K_DIM / 4) / 256, 256>>>(
        reinterpret_cast<const float4*>(x));
    transpose_w_kernel<<<dim3(N_DIM / 32, K_DIM / 32), dim3(32, 8)>>>(w);
    gemm_tf32_kernel<<<dim3(N_DIM / BN, M_DIM / BM), 256, SMEM_TOTAL>>>();
    scan_kernel<<<(B_DIM * H_DIM) / 128, 128>>>(x, wc, bias, out, out_size);
}

// round 8
// speedup vs baseline: 1.1208x; 1.1208x over previous
#include <cuda_runtime.h>
#include <cstdint>

// ---------------------------------------------------------------------------
// SRU forward on sm_100: tf32 mma.sync GEMM (R4-proven mainloop) + float2 scan.
// L=1024, B=16, D=HIDDEN=2048.
// ---------------------------------------------------------------------------

#define L_DIM 1024
#define B_DIM 16
#define D_DIM 2048
#define H_DIM 2048
#define M_DIM (L_DIM * B_DIM)   // 16384
#define N_DIM (3 * H_DIM)       // 6144
#define K_DIM D_DIM             // 2048

// GEMM tiling
#define BM 128
#define BN 256
#define BK 32
#define KITERS (K_DIM / BK)      // 64
#define STAGES 3

#define A_STAGE_BYTES (BM * 128)
#define B_STAGE_BYTES (BN * 128)
#define STAGE_BYTES (A_STAGE_BYTES + B_STAGE_BYTES)      // 48 KB
#define SMEM_TOTAL (STAGES * STAGE_BYTES)                // 144 KB

// ------------------------- device scratch (no mallocs) ----------------------
__device__ float g_A[(size_t)M_DIM * K_DIM];   // tf32-rounded x (MxK)
__device__ float g_B[(size_t)N_DIM * K_DIM];   // tf32-rounded W^T (NxK)
__device__ float g_U[(size_t)M_DIM * N_DIM];   // GEMM output U (interleaved)

// ------------------------------ PTX helpers ---------------------------------
__device__ __forceinline__ uint32_t smem_u32(const void* p) {
    uint32_t a;
    asm("{ .reg .u64 t; cvta.to.shared.u64 t, %1; cvt.u32.u64 %0, t; }"
        : "=r"(a) : "l"(p));
    return a;
}

__device__ __forceinline__ float tf32_rna(float x) {
    uint32_t u;
    asm("cvt.rna.tf32.f32 %0, %1;" : "=r"(u) : "f"(x));
    return __uint_as_float(u);
}

__device__ __forceinline__ void cp_async16(uint32_t smem_dst, const void* gmem_src) {
    size_t g = __cvta_generic_to_global(gmem_src);
    asm volatile("cp.async.cg.shared.global [%0], [%1], 16;"
                 :: "r"(smem_dst), "l"(g) : "memory");
}
__device__ __forceinline__ void cp_commit() {
    asm volatile("cp.async.commit_group;" ::: "memory");
}
__device__ __forceinline__ void cp_wait1() {
    asm volatile("cp.async.wait_group 1;" ::: "memory");
}

__device__ __forceinline__ uint32_t sw128(uint32_t off) {
    return off ^ ((off >> 3) & 0x70);
}

__device__ __forceinline__ void ldsm4(uint32_t* r, uint32_t addr) {
    asm volatile("ldmatrix.sync.aligned.m8n8.x4.shared.b16 {%0,%1,%2,%3}, [%4];"
                 : "=r"(r[0]), "=r"(r[1]), "=r"(r[2]), "=r"(r[3]) : "r"(addr));
}

__device__ __forceinline__ void mma_tf32(float* c, const uint32_t* a,
                                         uint32_t b0, uint32_t b1) {
    asm volatile(
        "mma.sync.aligned.m16n8k8.row.col.f32.tf32.tf32.f32 "
        "{%0,%1,%2,%3}, {%4,%5,%6,%7}, {%8,%9}, {%0,%1,%2,%3};"
        : "+f"(c[0]), "+f"(c[1]), "+f"(c[2]), "+f"(c[3])
        : "r"(a[0]), "r"(a[1]), "r"(a[2]), "r"(a[3]), "r"(b0), "r"(b1));
}

// --------------------------- prep kernels -----------------------------------
__global__ void conv_x_kernel(const float4* __restrict__ x) {
    int i = blockIdx.x * blockDim.x + threadIdx.x;
    float4 v = x[i];
    float4 o;
    o.x = tf32_rna(v.x); o.y = tf32_rna(v.y);
    o.z = tf32_rna(v.z); o.w = tf32_rna(v.w);
    reinterpret_cast<float4*>(g_A)[i] = o;
}

// W (K, N) fp32 -> g_B (N, K), tf32-rounded
__global__ void transpose_w_kernel(const float* __restrict__ w) {
    __shared__ float t[32][33];
    int n = blockIdx.x * 32 + threadIdx.x;
    int k0 = blockIdx.y * 32;
#pragma unroll
    for (int j = 0; j < 4; j++) {
        int k = k0 + threadIdx.y + j * 8;
        t[threadIdx.y + j * 8][threadIdx.x] = w[(size_t)k * N_DIM + n];
    }
    __syncthreads();
#pragma unroll
    for (int j = 0; j < 4; j++) {
        int nn = blockIdx.x * 32 + threadIdx.y + j * 8;
        g_B[(size_t)nn * K_DIM + k0 + threadIdx.x] =
            tf32_rna(t[threadIdx.x][threadIdx.y + j * 8]);
    }
}

// ----------------------------- GEMM kernel (R4-proven) -----------------------
// 256 threads, 8 warps in 2(M) x 4(N), warp tile 64x64, mma m16n8k8 tf32.
__device__ __forceinline__ void load_tile(int s, int kt, int m0, int n0,
                                          uint32_t sb, int tid) {
    uint32_t abase = sb + s * STAGE_BYTES;
    uint32_t bbase = abase + A_STAGE_BYTES;
    int k0 = kt * BK;
#pragma unroll
    for (int i = 0; i < 4; i++) {
        int idx = tid + i * 256;
        uint32_t off = idx * 16;
        int r = off >> 7;
        int c = off & 127;
        const char* src = (const char*)g_A + (((size_t)(m0 + r) * K_DIM + k0) * 4 + c);
        cp_async16(abase + sw128(off), src);
    }
#pragma unroll
    for (int i = 0; i < 8; i++) {
        int idx = tid + i * 256;
        uint32_t off = idx * 16;
        int r = off >> 7;
        int c = off & 127;
        const char* src = (const char*)g_B + (((size_t)(n0 + r) * K_DIM + k0) * 4 + c);
        cp_async16(bbase + sw128(off), src);
    }
}

__global__ void __launch_bounds__(256, 1)
gemm_tf32_kernel() {
    extern __shared__ char smem[];
    uint32_t sb = smem_u32(smem);
    int tid = threadIdx.x;
    int wid = tid >> 5;
    int lane = tid & 31;
    int n0 = blockIdx.x * BN;
    int m0 = blockIdx.y * BM;
    int wm = wid & 1;        // 0..1 (M)
    int wn = wid >> 1;       // 0..3 (N)

    int sub = lane >> 3;
    int r8 = lane & 7;
    uint32_t a_row = wm * 64 + ((sub & 1) << 3) + r8;
    uint32_t a_kb = (sub >> 1) * 16;
    uint32_t b_row = wn * 64 + ((sub >> 1) << 3) + r8;
    uint32_t b_kb = (sub & 1) * 16;

    float acc[4][8][4];
#pragma unroll
    for (int mt = 0; mt < 4; mt++)
#pragma unroll
        for (int nt = 0; nt < 8; nt++)
#pragma unroll
            for (int q = 0; q < 4; q++) acc[mt][nt][q] = 0.0f;

    load_tile(0, 0, m0, n0, sb, tid);
    cp_commit();
    load_tile(1, 1, m0, n0, sb, tid);
    cp_commit();

    for (int kt = 0; kt < KITERS; kt++) {
        int s = kt % STAGES;
        cp_wait1();
        __syncthreads();

        if (kt + 2 < KITERS) {
            load_tile((kt + 2) % STAGES, kt + 2, m0, n0, sb, tid);
        }
        cp_commit();

        uint32_t abase = sb + s * STAGE_BYTES;
        uint32_t bbase = abase + A_STAGE_BYTES;
#pragma unroll
        for (int ks = 0; ks < 4; ks++) {
            uint32_t af[4][4], bf[4][4];
#pragma unroll
            for (int mt = 0; mt < 4; mt++) {
                uint32_t off = (a_row + mt * 16) * 128 + ks * 32 + a_kb;
                ldsm4(af[mt], abase + sw128(off));
            }
#pragma unroll
            for (int np = 0; np < 4; np++) {
                uint32_t off = (b_row + np * 16) * 128 + ks * 32 + b_kb;
                ldsm4(bf[np], bbase + sw128(off));
            }
#pragma unroll
            for (int mt = 0; mt < 4; mt++)
#pragma unroll
                for (int nt = 0; nt < 8; nt++) {
                    uint32_t b0 = bf[nt >> 1][(nt & 1) * 2];
                    uint32_t b1 = bf[nt >> 1][(nt & 1) * 2 + 1];
                    mma_tf32(acc[mt][nt], af[mt], b0, b1);
                }
        }
    }

    // epilogue: direct STG (float2 per fragment half), interleaved U
    int g = lane >> 2;
    int tig = lane & 3;
#pragma unroll
    for (int mt = 0; mt < 4; mt++) {
        int row = m0 + wm * 64 + mt * 16 + g;
#pragma unroll
        for (int nt = 0; nt < 8; nt++) {
            int col = n0 + wn * 64 + nt * 8 + tig * 2;
            float* p0 = g_U + (size_t)row * N_DIM + col;
            float* p1 = g_U + (size_t)(row + 8) * N_DIM + col;
            *reinterpret_cast<float2*>(p0) =
                make_float2(acc[mt][nt][0], acc[mt][nt][1]);
            *reinterpret_cast<float2*>(p1) =
                make_float2(acc[mt][nt][2], acc[mt][nt][3]);
        }
    }
}

// ----------------------------- scan kernel -----------------------------------
// One thread handles TWO adjacent h lanes -> all traffic is 8B-vectorized:
// U rows give (u0,u1),(u2,u0'),(u1',u2') as three float2; x/out as float2.
__device__ __forceinline__ float sigm(float z) {
    return __fdividef(1.0f, 1.0f + __expf(-z));
}

#define SBLK 8

__global__ void __launch_bounds__(128)
scan_kernel(const float* __restrict__ x, const float* __restrict__ wc,
            const float* __restrict__ bias, float* __restrict__ out,
            int out_size) {
    int gidx = blockIdx.x * blockDim.x + threadIdx.x;  // 0..16383
    int b = gidx >> 10;                 // batch
    int hp = (gidx & 1023) << 1;        // even h base
    float wcf0 = wc[hp],          wcf1 = wc[hp + 1];
    float wcr0 = wc[H_DIM + hp],  wcr1 = wc[H_DIM + hp + 1];
    float bf0 = bias[hp],         bf1 = bias[hp + 1];
    float br0 = bias[H_DIM + hp], br1 = bias[H_DIM + hp + 1];
    const float sx = 1.7320508075688772f;  // sqrt(1 + 2*exp(0))

    const float2* Ub = reinterpret_cast<const float2*>(
        g_U + (size_t)b * N_DIM + 3 * hp);
    const float2* xb = reinterpret_cast<const float2*>(
        x + (size_t)b * D_DIM + hp);
    float2* ob = reinterpret_cast<float2*>(out + (size_t)b * H_DIM + hp);
    const size_t Ustep = (size_t)B_DIM * N_DIM / 2;   // float2 units per l
    const size_t xstep = (size_t)B_DIM * D_DIM / 2;
    const size_t ostep = (size_t)B_DIM * H_DIM / 2;

    float2 A[SBLK][4], Bv[SBLK][4];

#define LOADBLK(l0, dst)                                                   \
    {                                                                      \
        size_t ou_ = (size_t)(l0) * Ustep;                                 \
        size_t ox_ = (size_t)(l0) * xstep;                                 \
        _Pragma("unroll") for (int i = 0; i < SBLK; i++) {                 \
            dst[i][0] = Ub[ou_];                                           \
            dst[i][1] = Ub[ou_ + 1];                                       \
            dst[i][2] = Ub[ou_ + 2];                                       \
            dst[i][3] = xb[ox_];                                           \
            ou_ += Ustep; ox_ += xstep;                                    \
        }                                                                  \
    }

#define COMPBLK(l0, src)                                                   \
    {                                                                      \
        float2* op_ = ob + (size_t)(l0) * ostep;                           \
        _Pragma("unroll") for (int i = 0; i < SBLK; i++) {                 \
            float u0a = src[i][0].x, u1a = src[i][0].y;                    \
            float u2a = src[i][1].x, u0b = src[i][1].y;                    \
            float u1b = src[i][2].x, u2b = src[i][2].y;                    \
            float xva = src[i][3].x * sx, xvb = src[i][3].y * sx;          \
            float f0 = sigm(fmaf(c0, wcf0, u1a + bf0));                    \
            c0 = fmaf(c0 - u0a, f0, u0a);                                  \
            float r0 = sigm(fmaf(c0, wcr0, u2a + br0));                    \
            float h0 = fmaf(c0 - xva, r0, xva);                            \
            float f1 = sigm(fmaf(c1, wcf1, u1b + bf1));                    \
            c1 = fmaf(c1 - u0b, f1, u0b);                                  \
            float r1 = sigm(fmaf(c1, wcr1, u2b + br1));                    \
            float h1 = fmaf(c1 - xvb, r1, xvb);                            \
            *op_ = make_float2(h0, h1);                                    \
            op_ += ostep;                                                  \
        }                                                                  \
    }

    float c0 = 0.0f, c1 = 0.0f;
    LOADBLK(0, A);
    for (int l0 = 0; l0 < L_DIM; l0 += 2 * SBLK) {
        LOADBLK(l0 + SBLK, Bv);
        COMPBLK(l0, A);
        if (l0 + 2 * SBLK < L_DIM) {
            LOADBLK(l0 + 2 * SBLK, A);
        }
        COMPBLK(l0 + SBLK, Bv);
    }

    if (out_size >= M_DIM * H_DIM + B_DIM * H_DIM) {
        reinterpret_cast<float2*>(out + (size_t)M_DIM * H_DIM)
            [(size_t)b * (H_DIM / 2) + (hp >> 1)] = make_float2(c0, c1);
    }
}

// ------------------------------ launcher ------------------------------------
extern "C" void kernel_launch(void* const* d_in, const int* in_sizes, int n_in,
                              void* d_out, int out_size) {
    (void)in_sizes; (void)n_in;
    const float* x    = (const float*)d_in[0];
    const float* w    = (const float*)d_in[1];
    const float* wc   = (const float*)d_in[2];
    const float* bias = (const float*)d_in[3];
    float* out = (float*)d_out;

    cudaFuncSetAttribute(gemm_tf32_kernel,
                         cudaFuncAttributeMaxDynamicSharedMemorySize, SMEM_TOTAL);

    conv_x_kernel<<<(M_DIM * K_DIM / 4) / 256, 256>>>(
        reinterpret_cast<const float4*>(x));
    transpose_w_kernel<<<dim3(N_DIM / 32, K_DIM / 32), dim3(32, 8)>>>(w);
    gemm_tf32_kernel<<<dim3(N_DIM / BN, M_DIM / BM), 256, SMEM_TOTAL>>>();
    scan_kernel<<<(B_DIM * H_DIM / 2) / 128, 128>>>(x, wc, bias, out, out_size);
}

// round 11
// speedup vs baseline: 1.2317x; 1.0989x over previous
#include <cuda_runtime.h>
#include <cstdint>

// ---------------------------------------------------------------------------
// SRU forward on sm_100: tf32 mma.sync GEMM (128x128 tile, 2 CTAs/SM) + scan.
// L=1024, B=16, D=HIDDEN=2048.
// ---------------------------------------------------------------------------

#define L_DIM 1024
#define B_DIM 16
#define D_DIM 2048
#define H_DIM 2048
#define M_DIM (L_DIM * B_DIM)   // 16384
#define N_DIM (3 * H_DIM)       // 6144
#define K_DIM D_DIM             // 2048

// GEMM tiling
#define BM 128
#define BN 128
#define BK 32
#define KITERS (K_DIM / BK)      // 64
#define STAGES 3

#define A_STAGE_BYTES (BM * 128)             // 16 KB
#define B_STAGE_BYTES (BN * 128)             // 16 KB
#define STAGE_BYTES (A_STAGE_BYTES + B_STAGE_BYTES)      // 32 KB
#define SMEM_TOTAL (STAGES * STAGE_BYTES)                // 96 KB -> 2 CTAs/SM

// ------------------------- device scratch (no mallocs) ----------------------
__device__ float g_A[(size_t)M_DIM * K_DIM];   // tf32-rounded x (MxK)
__device__ float g_B[(size_t)N_DIM * K_DIM];   // tf32-rounded W^T (NxK)
__device__ float g_U[(size_t)M_DIM * N_DIM];   // GEMM output U (interleaved)

// ------------------------------ PTX helpers ---------------------------------
__device__ __forceinline__ uint32_t smem_u32(const void* p) {
    uint32_t a;
    asm("{ .reg .u64 t; cvta.to.shared.u64 t, %1; cvt.u32.u64 %0, t; }"
        : "=r"(a) : "l"(p));
    return a;
}

__device__ __forceinline__ float tf32_rna(float x) {
    uint32_t u;
    asm("cvt.rna.tf32.f32 %0, %1;" : "=r"(u) : "f"(x));
    return __uint_as_float(u);
}

__device__ __forceinline__ void cp_async16(uint32_t smem_dst, const void* gmem_src) {
    size_t g = __cvta_generic_to_global(gmem_src);
    asm volatile("cp.async.cg.shared.global [%0], [%1], 16;"
                 :: "r"(smem_dst), "l"(g) : "memory");
}
__device__ __forceinline__ void cp_commit() {
    asm volatile("cp.async.commit_group;" ::: "memory");
}
__device__ __forceinline__ void cp_wait1() {
    asm volatile("cp.async.wait_group 1;" ::: "memory");
}

__device__ __forceinline__ uint32_t sw128(uint32_t off) {
    return off ^ ((off >> 3) & 0x70);
}

__device__ __forceinline__ void ldsm4(uint32_t* r, uint32_t addr) {
    asm volatile("ldmatrix.sync.aligned.m8n8.x4.shared.b16 {%0,%1,%2,%3}, [%4];"
                 : "=r"(r[0]), "=r"(r[1]), "=r"(r[2]), "=r"(r[3]) : "r"(addr));
}

__device__ __forceinline__ void mma_tf32(float* c, const uint32_t* a,
                                         uint32_t b0, uint32_t b1) {
    asm volatile(
        "mma.sync.aligned.m16n8k8.row.col.f32.tf32.tf32.f32 "
        "{%0,%1,%2,%3}, {%4,%5,%6,%7}, {%8,%9}, {%0,%1,%2,%3};"
        : "+f"(c[0]), "+f"(c[1]), "+f"(c[2]), "+f"(c[3])
        : "r"(a[0]), "r"(a[1]), "r"(a[2]), "r"(a[3]), "r"(b0), "r"(b1));
}

// --------------------------- prep kernels -----------------------------------
__global__ void conv_x_kernel(const float4* __restrict__ x) {
    int i = blockIdx.x * blockDim.x + threadIdx.x;
    float4 v = x[i];
    float4 o;
    o.x = tf32_rna(v.x); o.y = tf32_rna(v.y);
    o.z = tf32_rna(v.z); o.w = tf32_rna(v.w);
    reinterpret_cast<float4*>(g_A)[i] = o;
}

// W (K, N) fp32 -> g_B (N, K), tf32-rounded
__global__ void transpose_w_kernel(const float* __restrict__ w) {
    __shared__ float t[32][33];
    int n = blockIdx.x * 32 + threadIdx.x;
    int k0 = blockIdx.y * 32;
#pragma unroll
    for (int j = 0; j < 4; j++) {
        int k = k0 + threadIdx.y + j * 8;
        t[threadIdx.y + j * 8][threadIdx.x] = w[(size_t)k * N_DIM + n];
    }
    __syncthreads();
#pragma unroll
    for (int j = 0; j < 4; j++) {
        int nn = blockIdx.x * 32 + threadIdx.y + j * 8;
        g_B[(size_t)nn * K_DIM + k0 + threadIdx.x] =
            tf32_rna(t[threadIdx.x][threadIdx.y + j * 8]);
    }
}

// ----------------------------- GEMM kernel ----------------------------------
// 256 threads, 8 warps in 2(M) x 4(N), warp tile 64x32, mma m16n8k8 tf32.
// 2 CTAs/SM (96 KB smem, <=128 regs).
__device__ __forceinline__ void load_tile(int s, int kt, int m0, int n0,
                                          uint32_t sb, int tid) {
    uint32_t abase = sb + s * STAGE_BYTES;
    uint32_t bbase = abase + A_STAGE_BYTES;
    int k0 = kt * BK;
    // A tile: 128 rows x 128B (1024 chunks of 16B, 256 threads -> 4 each)
#pragma unroll
    for (int i = 0; i < 4; i++) {
        int idx = tid + i * 256;
        uint32_t off = idx * 16;
        int r = off >> 7;
        int c = off & 127;
        const char* src = (const char*)g_A + (((size_t)(m0 + r) * K_DIM + k0) * 4 + c);
        cp_async16(abase + sw128(off), src);
    }
    // B tile: 128 rows x 128B
#pragma unroll
    for (int i = 0; i < 4; i++) {
        int idx = tid + i * 256;
        uint32_t off = idx * 16;
        int r = off >> 7;
        int c = off & 127;
        const char* src = (const char*)g_B + (((size_t)(n0 + r) * K_DIM + k0) * 4 + c);
        cp_async16(bbase + sw128(off), src);
    }
}

__global__ void __launch_bounds__(256, 2)
gemm_tf32_kernel() {
    extern __shared__ char smem[];
    uint32_t sb = smem_u32(smem);
    int tid = threadIdx.x;
    int wid = tid >> 5;
    int lane = tid & 31;
    int n0 = blockIdx.x * BN;
    int m0 = blockIdx.y * BM;
    int wm = wid & 1;        // 0..1 (M, x64)
    int wn = wid >> 1;       // 0..3 (N, x32)

    int sub = lane >> 3;
    int r8 = lane & 7;
    uint32_t a_row = wm * 64 + ((sub & 1) << 3) + r8;   // + mt*16
    uint32_t a_kb = (sub >> 1) * 16;                    // + ks*32
    uint32_t b_row = wn * 32 + ((sub >> 1) << 3) + r8;  // + np*16
    uint32_t b_kb = (sub & 1) * 16;                     // + ks*32

    float acc[4][4][4];
#pragma unroll
    for (int mt = 0; mt < 4; mt++)
#pragma unroll
        for (int nt = 0; nt < 4; nt++)
#pragma unroll
            for (int q = 0; q < 4; q++) acc[mt][nt][q] = 0.0f;

    load_tile(0, 0, m0, n0, sb, tid);
    cp_commit();
    load_tile(1, 1, m0, n0, sb, tid);
    cp_commit();

    for (int kt = 0; kt < KITERS; kt++) {
        int s = kt % STAGES;
        cp_wait1();
        __syncthreads();

        if (kt + 2 < KITERS) {
            load_tile((kt + 2) % STAGES, kt + 2, m0, n0, sb, tid);
        }
        cp_commit();

        uint32_t abase = sb + s * STAGE_BYTES;
        uint32_t bbase = abase + A_STAGE_BYTES;
#pragma unroll
        for (int ks = 0; ks < 4; ks++) {
            uint32_t af[4][4], bf[2][4];
#pragma unroll
            for (int mt = 0; mt < 4; mt++) {
                uint32_t off = (a_row + mt * 16) * 128 + ks * 32 + a_kb;
                ldsm4(af[mt], abase + sw128(off));
            }
#pragma unroll
            for (int np = 0; np < 2; np++) {
                uint32_t off = (b_row + np * 16) * 128 + ks * 32 + b_kb;
                ldsm4(bf[np], bbase + sw128(off));
            }
#pragma unroll
            for (int mt = 0; mt < 4; mt++)
#pragma unroll
                for (int nt = 0; nt < 4; nt++) {
                    uint32_t b0 = bf[nt >> 1][(nt & 1) * 2];
                    uint32_t b1 = bf[nt >> 1][(nt & 1) * 2 + 1];
                    mma_tf32(acc[mt][nt], af[mt], b0, b1);
                }
        }
    }

    // epilogue: direct STG (float2 per fragment half), interleaved U
    int g = lane >> 2;
    int tig = lane & 3;
#pragma unroll
    for (int mt = 0; mt < 4; mt++) {
        int row = m0 + wm * 64 + mt * 16 + g;
#pragma unroll
        for (int nt = 0; nt < 4; nt++) {
            int col = n0 + wn * 32 + nt * 8 + tig * 2;
            float* p0 = g_U + (size_t)row * N_DIM + col;
            float* p1 = g_U + (size_t)(row + 8) * N_DIM + col;
            *reinterpret_cast<float2*>(p0) =
                make_float2(acc[mt][nt][0], acc[mt][nt][1]);
            *reinterpret_cast<float2*>(p1) =
                make_float2(acc[mt][nt][2], acc[mt][nt][3]);
        }
    }
}

// ----------------------------- scan kernel (R4-proven) -----------------------
__device__ __forceinline__ float sigm(float z) {
    return __fdividef(1.0f, 1.0f + __expf(-z));
}

#define SBLK 8

__global__ void __launch_bounds__(128)
scan_kernel(const float* __restrict__ x, const float* __restrict__ wc,
            const float* __restrict__ bias, float* __restrict__ out,
            int out_size) {
    int gidx = blockIdx.x * blockDim.x + threadIdx.x;  // 0..32767
    int b = gidx >> 11;
    int h = gidx & 2047;
    float wcf = wc[h];
    float wcr = wc[H_DIM + h];
    float bf = bias[h];
    float br = bias[H_DIM + h];
    const float sx = 1.7320508075688772f;  // sqrt(1 + 2*exp(0))

    const float* Ubase = g_U + (size_t)b * N_DIM + 3 * h;
    const float* xbase = x + (size_t)b * D_DIM + h;
    float* obase = out + (size_t)b * H_DIM + h;
    const size_t Ustep = (size_t)B_DIM * N_DIM;
    const size_t xstep = (size_t)B_DIM * D_DIM;

    float A0[SBLK], A1[SBLK], A2[SBLK], A3[SBLK];
    float Bb0[SBLK], Bb1[SBLK], Bb2[SBLK], Bb3[SBLK];

#define LOADBLK(l0, d0, d1, d2, d3)                                        \
    {                                                                      \
        const float* Up_ = Ubase + (size_t)(l0) * Ustep;                   \
        const float* xp_ = xbase + (size_t)(l0) * xstep;                   \
        _Pragma("unroll") for (int i = 0; i < SBLK; i++) {                 \
            d0[i] = Up_[0]; d1[i] = Up_[1]; d2[i] = Up_[2];                \
            d3[i] = *xp_;                                                  \
            Up_ += Ustep; xp_ += xstep;                                    \
        }                                                                  \
    }

#define COMPBLK(l0, d0, d1, d2, d3)                                        \
    {                                                                      \
        float* op_ = obase + (size_t)(l0) * ((size_t)B_DIM * H_DIM);       \
        _Pragma("unroll") for (int i = 0; i < SBLK; i++) {                 \
            float u0 = d0[i];                                              \
            float u1 = d1[i] + bf;                                         \
            float u2 = d2[i] + br;                                         \
            float xv = d3[i] * sx;                                         \
            float f = sigm(fmaf(c, wcf, u1));                              \
            c = fmaf(c - u0, f, u0);                                       \
            float r = sigm(fmaf(c, wcr, u2));                              \
            *op_ = fmaf(c - xv, r, xv);                                    \
            op_ += (size_t)B_DIM * H_DIM;                                  \
        }                                                                  \
    }

    float c = 0.0f;
    LOADBLK(0, A0, A1, A2, A3);
    for (int l0 = 0; l0 < L_DIM; l0 += 2 * SBLK) {
        LOADBLK(l0 + SBLK, Bb0, Bb1, Bb2, Bb3);
        COMPBLK(l0, A0, A1, A2, A3);
        if (l0 + 2 * SBLK < L_DIM) {
            LOADBLK(l0 + 2 * SBLK, A0, A1, A2, A3);
        }
        COMPBLK(l0 + SBLK, Bb0, Bb1, Bb2, Bb3);
    }

    if (out_size >= M_DIM * H_DIM + B_DIM * H_DIM) {
        out[(size_t)M_DIM * H_DIM + gidx] = c;  // c_last
    }
}

// ------------------------------ launcher ------------------------------------
extern "C" void kernel_launch(void* const* d_in, const int* in_sizes, int n_in,
                              void* d_out, int out_size) {
    (void)in_sizes; (void)n_in;
    const float* x    = (const float*)d_in[0];
    const float* w    = (const float*)d_in[1];
    const float* wc   = (const float*)d_in[2];
    const float* bias = (const float*)d_in[3];
    float* out = (float*)d_out;

    cudaFuncSetAttribute(gemm_tf32_kernel,
                         cudaFuncAttributeMaxDynamicSharedMemorySize, SMEM_TOTAL);

    conv_x_kernel<<<(M_DIM * K_DIM / 4) / 256, 256>>>(
        reinterpret_cast<const float4*>(x));
    transpose_w_kernel<<<dim3(N_DIM / 32, K_DIM / 32), dim3(32, 8)>>>(w);
    gemm_tf32_kernel<<<dim3(N_DIM / BN, M_DIM / BM), 256, SMEM_TOTAL>>>();
    scan_kernel<<<(B_DIM * H_DIM) / 128, 128>>>(x, wc, bias, out, out_size);
}